// round 1
// baseline (speedup 1.0000x reference)
#include <cuda_runtime.h>
#include <math.h>

// Problem constants
#define BB   16
#define TT   512
#define HH   384
#define FF   384
#define KK3  3
#define DMAX 8
#define LL   (TT * DMAX)          // 4096
#define BT   (BB * TT)            // 8192
#define KKT  (HH * KK3)           // 1152 unified reduction dim
#define H4   (HH / 4)             // 96 float4 per row
#define OUT_OFF ((size_t)BB * LL * HH)   // length[] offset in d_out

// Scratch (static device globals; no allocation allowed)
__device__ float g_wt1[KKT * FF];       // conv1 weights as [kk][f]
__device__ float g_wt2[KKT * FF];       // conv2 weights as [kk][f]
__device__ float g_h1[BT * FF];         // conv1 output
__device__ float g_h2[BT * FF];         // conv2 output
__device__ int   g_tok[BB * LL];        // token index per expanded position (-1 = pad)

// ---------------------------------------------------------------------------
// Weight transpose: w[f,c,tap] (OIW) -> wt[(tap*384+c)*384 + f]
// ---------------------------------------------------------------------------
__global__ void wtrans_kernel(const float* __restrict__ w, float* __restrict__ wt) {
    int idx = blockIdx.x * 256 + threadIdx.x;
    if (idx >= FF * HH * KK3) return;
    int tap = idx % 3;
    int c   = (idx / 3) % HH;
    int f   = idx / (3 * HH);
    wt[(tap * HH + c) * FF + f] = w[idx];
}

// ---------------------------------------------------------------------------
// Conv-as-GEMM: C[m,f] = sum_{tap,c} A[b, t+tap-1, c] * wt[tap*384+c, f] + bias[f]
// Tiles: BM=64, BN=64, BK=16. 256 threads, 4x4 per thread. fp32.
// M tiles are 64 rows within a batch (512 % 64 == 0), so the only boundary
// handling is zero-padding rows t<0 / t>=512 per tap.
// ---------------------------------------------------------------------------
__global__ void __launch_bounds__(256) conv_gemm_kernel(
    const float* __restrict__ A, const float* __restrict__ Bw,
    const float* __restrict__ bias, float* __restrict__ C) {
    __shared__ float As[16][64];
    __shared__ float Bs[16][64];

    const int tid = threadIdx.x;
    const int tx = tid & 15;          // 0..15 -> 4 F columns each
    const int ty = tid >> 4;          // 0..15 -> 4 M rows each
    const int m0 = blockIdx.y * 64;
    const int f0 = blockIdx.x * 64;
    const int t0 = m0 & (TT - 1);     // t within batch (tiles are batch-aligned)

    const int a_mi = tid >> 2;        // 0..63 (row within tile)
    const int a_kq = (tid & 3) << 2;  // 0,4,8,12 (k offset, float4)
    const int b_ki = tid >> 4;        // 0..15 (k row)
    const int b_f  = (tid & 15) << 2; // 0..60 (f offset, float4)

    float acc[4][4] = {};

    for (int kt = 0; kt < KKT / 16; kt++) {       // 72 steps; 24 per tap
        const int tap = kt / 24;                  // 0,1,2 (uniform in block)
        const int c0  = (kt - tap * 24) << 4;     // 0..368

        // Load A tile (with time shift + zero pad at batch edges)
        float4 av = make_float4(0.f, 0.f, 0.f, 0.f);
        const int trow = t0 + a_mi + tap - 1;
        if (trow >= 0 && trow < TT) {
            av = *reinterpret_cast<const float4*>(
                A + (size_t)(m0 + a_mi + tap - 1) * HH + c0 + a_kq);
        }
        // Load B tile (coalesced: f contiguous)
        const float4 bv = *reinterpret_cast<const float4*>(
            Bw + (size_t)(tap * HH + c0 + b_ki) * FF + f0 + b_f);

        __syncthreads();
        As[a_kq + 0][a_mi] = av.x;
        As[a_kq + 1][a_mi] = av.y;
        As[a_kq + 2][a_mi] = av.z;
        As[a_kq + 3][a_mi] = av.w;
        *reinterpret_cast<float4*>(&Bs[b_ki][b_f]) = bv;
        __syncthreads();

#pragma unroll
        for (int k = 0; k < 16; k++) {
            const float4 a = *reinterpret_cast<const float4*>(&As[k][ty << 2]);
            const float4 b = *reinterpret_cast<const float4*>(&Bs[k][tx << 2]);
            acc[0][0] += a.x * b.x; acc[0][1] += a.x * b.y; acc[0][2] += a.x * b.z; acc[0][3] += a.x * b.w;
            acc[1][0] += a.y * b.x; acc[1][1] += a.y * b.y; acc[1][2] += a.y * b.z; acc[1][3] += a.y * b.w;
            acc[2][0] += a.z * b.x; acc[2][1] += a.z * b.y; acc[2][2] += a.z * b.z; acc[2][3] += a.z * b.w;
            acc[3][0] += a.w * b.x; acc[3][1] += a.w * b.y; acc[3][2] += a.w * b.z; acc[3][3] += a.w * b.w;
        }
    }

    const float4 bias4 = *reinterpret_cast<const float4*>(bias + f0 + (tx << 2));
#pragma unroll
    for (int i = 0; i < 4; i++) {
        float4 o;
        o.x = acc[i][0] + bias4.x;
        o.y = acc[i][1] + bias4.y;
        o.z = acc[i][2] + bias4.z;
        o.w = acc[i][3] + bias4.w;
        *reinterpret_cast<float4*>(
            C + (size_t)(m0 + (ty << 2) + i) * FF + f0 + (tx << 2)) = o;
    }
}

// ---------------------------------------------------------------------------
// Block reduction helper: 128 threads (4 warps)
// ---------------------------------------------------------------------------
__device__ __forceinline__ float block_sum128(float v, float* red, int tid) {
#pragma unroll
    for (int o = 16; o > 0; o >>= 1) v += __shfl_xor_sync(0xffffffffu, v, o);
    if ((tid & 31) == 0) red[tid >> 5] = v;
    __syncthreads();
    v = red[0] + red[1] + red[2] + red[3];
    __syncthreads();
    return v;
}

__device__ __forceinline__ float gelu_exact(float y) {
    return 0.5f * y * (1.0f + erff(y * 0.70710678118654752f));
}

// LayerNorm + exact GELU in place. One block per row, 128 threads (3 elems each).
__global__ void __launch_bounds__(128) ln_gelu_kernel(
    float* __restrict__ h, const float* __restrict__ g, const float* __restrict__ bb) {
    __shared__ float red[4];
    const int row = blockIdx.x, tid = threadIdx.x;
    float* p = h + (size_t)row * FF;
    float v0 = p[tid], v1 = p[tid + 128], v2 = p[tid + 256];
    const float mu = block_sum128(v0 + v1 + v2, red, tid) * (1.0f / FF);
    const float d0 = v0 - mu, d1 = v1 - mu, d2 = v2 - mu;
    const float var = block_sum128(d0 * d0 + d1 * d1 + d2 * d2, red, tid) * (1.0f / FF);
    const float rs = rsqrtf(var + 1e-5f);
    const float y0 = d0 * rs * g[tid] + bb[tid];
    const float y1 = d1 * rs * g[tid + 128] + bb[tid + 128];
    const float y2 = d2 * rs * g[tid + 256] + bb[tid + 256];
    p[tid]       = gelu_exact(y0);
    p[tid + 128] = gelu_exact(y1);
    p[tid + 256] = gelu_exact(y2);
}

// LayerNorm + GELU + linear(384->1) + ReLU -> length[row]
__global__ void __launch_bounds__(128) ln_gelu_lin_kernel(
    const float* __restrict__ h, const float* __restrict__ g, const float* __restrict__ bb,
    const float* __restrict__ lw, const float* __restrict__ lb, float* __restrict__ lenout) {
    __shared__ float red[4];
    const int row = blockIdx.x, tid = threadIdx.x;
    const float* p = h + (size_t)row * FF;
    float v0 = p[tid], v1 = p[tid + 128], v2 = p[tid + 256];
    const float mu = block_sum128(v0 + v1 + v2, red, tid) * (1.0f / FF);
    const float d0 = v0 - mu, d1 = v1 - mu, d2 = v2 - mu;
    const float var = block_sum128(d0 * d0 + d1 * d1 + d2 * d2, red, tid) * (1.0f / FF);
    const float rs = rsqrtf(var + 1e-5f);
    const float q0 = gelu_exact(d0 * rs * g[tid] + bb[tid]);
    const float q1 = gelu_exact(d1 * rs * g[tid + 128] + bb[tid + 128]);
    const float q2 = gelu_exact(d2 * rs * g[tid + 256] + bb[tid + 256]);
    const float dot = block_sum128(q0 * lw[tid] + q1 * lw[tid + 128] + q2 * lw[tid + 256],
                                   red, tid);
    if (tid == 0) lenout[row] = fmaxf(dot + lb[0], 0.0f);
}

// ---------------------------------------------------------------------------
// Duration scan + token map. One block per batch, 512 threads.
// ---------------------------------------------------------------------------
__global__ void __launch_bounds__(512) build_tok_kernel(
    const float* __restrict__ td, int* __restrict__ tok) {
    __shared__ int sc[TT];
    const int b = blockIdx.x, t = threadIdx.x;
    const int d = (int)rintf(expf(td[b * TT + t]));
    sc[t] = d;
    __syncthreads();
    // Hillis-Steele inclusive scan
    for (int off = 1; off < TT; off <<= 1) {
        int v = sc[t];
        int add = (t >= off) ? sc[t - off] : 0;
        __syncthreads();
        sc[t] = v + add;
        __syncthreads();
    }
    const int end = sc[t];
    const int start = end - d;
    for (int l = start; l < end; l++) tok[b * LL + l] = t;
    __syncthreads();
    const int total = sc[TT - 1];
    for (int l = total + t; l < LL; l += TT) tok[b * LL + l] = -1;
}

// ---------------------------------------------------------------------------
// Expansion: out[b,l,:] = x[b,tok[b][l],:] (or zeros). float4 per thread.
// 16*4096*96 = 6,291,456 float4s = 24576 blocks * 256 threads exactly.
// ---------------------------------------------------------------------------
__global__ void __launch_bounds__(256) expand_kernel(
    const float* __restrict__ x, const int* __restrict__ tok, float* __restrict__ out) {
    const unsigned idx = blockIdx.x * 256u + threadIdx.x;
    const int h4 = idx % H4;
    const int l  = (idx / H4) & (LL - 1);
    const int b  = idx / (H4 * LL);
    const int t  = tok[b * LL + l];
    float4 v = make_float4(0.f, 0.f, 0.f, 0.f);
    if (t >= 0)
        v = reinterpret_cast<const float4*>(x)[(size_t)(b * TT + t) * H4 + h4];
    reinterpret_cast<float4*>(out)[idx] = v;
}

// ---------------------------------------------------------------------------
extern "C" void kernel_launch(void* const* d_in, const int* in_sizes, int n_in,
                              void* d_out, int out_size) {
    const float* x   = (const float*)d_in[0];
    const float* td  = (const float*)d_in[1];
    const float* w1  = (const float*)d_in[2];
    const float* b1  = (const float*)d_in[3];
    const float* g1  = (const float*)d_in[4];
    const float* bb1 = (const float*)d_in[5];
    const float* w2  = (const float*)d_in[6];
    const float* b2  = (const float*)d_in[7];
    const float* g2  = (const float*)d_in[8];
    const float* bb2 = (const float*)d_in[9];
    const float* lw  = (const float*)d_in[10];
    const float* lb  = (const float*)d_in[11];

    float* out = (float*)d_out;
    float* lenout = out + OUT_OFF;

    float *wt1p, *wt2p, *h1p, *h2p;
    int* tokp;
    cudaGetSymbolAddress((void**)&wt1p, g_wt1);
    cudaGetSymbolAddress((void**)&wt2p, g_wt2);
    cudaGetSymbolAddress((void**)&h1p,  g_h1);
    cudaGetSymbolAddress((void**)&h2p,  g_h2);
    cudaGetSymbolAddress((void**)&tokp, g_tok);

    const int wele = FF * HH * KK3;
    wtrans_kernel<<<(wele + 255) / 256, 256>>>(w1, wt1p);
    wtrans_kernel<<<(wele + 255) / 256, 256>>>(w2, wt2p);

    dim3 ggrid(FF / 64, BT / 64);   // (6, 128)
    conv_gemm_kernel<<<ggrid, 256>>>(x, wt1p, b1, h1p);
    ln_gelu_kernel<<<BT, 128>>>(h1p, g1, bb1);
    conv_gemm_kernel<<<ggrid, 256>>>(h1p, wt2p, b2, h2p);
    ln_gelu_lin_kernel<<<BT, 128>>>(h2p, g2, bb2, lw, lb, lenout);

    build_tok_kernel<<<BB, TT>>>(td, tokp);
    expand_kernel<<<(BB * LL * H4) / 256, 256>>>(x, tokp, out);
}

// round 2
// speedup vs baseline: 2.5778x; 2.5778x over previous
#include <cuda_runtime.h>
#include <math.h>

// Problem constants
#define BB   16
#define TT   512
#define HH   384
#define FF   384
#define KK3  3
#define DMAX 8
#define LL   (TT * DMAX)          // 4096
#define BT   (BB * TT)            // 8192
#define KKT  (HH * KK3)           // 1152 unified reduction dim
#define H4   (HH / 4)             // 96 float4 per row
#define OUT_OFF ((size_t)BB * LL * HH)   // length[] offset in d_out

// GEMM tiling
#define BM 128
#define BN 64
#define BK 32
#define ASTR 36                   // A smem row stride (pad: banks 4r+c distinct)
#define BSTR 72                   // B smem row stride (pad: banks 8k+n distinct)

// Scratch (static device globals; no allocation allowed)
__device__ float g_wt1[KKT * FF];       // conv1 weights as [kk][f]
__device__ float g_wt2[KKT * FF];       // conv2 weights as [kk][f]
__device__ float g_h1[BT * FF];         // conv1 output
__device__ float g_h2[BT * FF];         // conv2 output
__device__ int   g_tok[BB * LL];        // token index per expanded position (-1 = pad)

// ---------------------------------------------------------------------------
// Weight transpose: w[f,c,tap] (OIW) -> wt[(tap*384+c)*384 + f]
// ---------------------------------------------------------------------------
__global__ void wtrans_kernel(const float* __restrict__ w, float* __restrict__ wt) {
    int idx = blockIdx.x * 256 + threadIdx.x;
    if (idx >= FF * HH * KK3) return;
    int tap = idx % 3;
    int c   = (idx / 3) % HH;
    int f   = idx / (3 * HH);
    wt[(tap * HH + c) * FF + f] = w[idx];
}

// ---------------------------------------------------------------------------
// tf32 round-to-nearest helper (result is fp32 bits with low mantissa zeroed)
// ---------------------------------------------------------------------------
__device__ __forceinline__ unsigned f2tf(float x) {
    unsigned r;
    asm("cvt.rna.tf32.f32 %0, %1;" : "=r"(r) : "f"(x));
    return r;
}

__device__ __forceinline__ void mma_tf32(float c[4], const unsigned a[4], const unsigned b[2]) {
    asm volatile(
        "mma.sync.aligned.m16n8k8.row.col.f32.tf32.tf32.f32 "
        "{%0,%1,%2,%3}, {%4,%5,%6,%7}, {%8,%9}, {%0,%1,%2,%3};\n"
        : "+f"(c[0]), "+f"(c[1]), "+f"(c[2]), "+f"(c[3])
        : "r"(a[0]), "r"(a[1]), "r"(a[2]), "r"(a[3]), "r"(b[0]), "r"(b[1]));
}

// ---------------------------------------------------------------------------
// Conv-as-GEMM with tf32 tensor cores.
// C[m,f] = sum_{tap,c} A[b, t+tap-1, c] * wt[tap*384+c, f] + bias[f]
// Grid (FF/BN=6, BT/BM=64), 256 threads (8 warps: 4 along M x 2 along N),
// each warp computes a 32x32 tile via m16n8k8 tf32 mma.
// M tiles are batch-aligned (512 % 128 == 0); zero-pad rows t<0 / t>=512.
// ---------------------------------------------------------------------------
__global__ void __launch_bounds__(256) conv_gemm_tf32_kernel(
    const float* __restrict__ A, const float* __restrict__ Bw,
    const float* __restrict__ bias, float* __restrict__ C) {
    __shared__ unsigned As[BM][ASTR];   // [m][k] tf32 bits
    __shared__ unsigned Bs[BK][BSTR];   // [k][n] tf32 bits

    const int tid  = threadIdx.x;
    const int lane = tid & 31;
    const int warp = tid >> 5;
    const int m0w  = (warp & 3) * 32;
    const int n0w  = (warp >> 2) * 32;
    const int m0   = blockIdx.y * BM;
    const int f0   = blockIdx.x * BN;
    const int b    = m0 >> 9;          // batch
    const int t0   = m0 & (TT - 1);    // t within batch

    const int r = lane >> 2;           // 0..7
    const int q = lane & 3;            // 0..3

    float acc[2][4][4];
#pragma unroll
    for (int mt = 0; mt < 2; mt++)
#pragma unroll
        for (int nt = 0; nt < 4; nt++)
#pragma unroll
            for (int i = 0; i < 4; i++) acc[mt][nt][i] = 0.0f;

    // A-fill indices: 1024 float4/iter -> 4 per thread
    const int a_m   = tid >> 1;              // handled rows: tid/2, +... (see below)
    // We use: q4 id = tid + 256*i ; m = q4>>3, k4 = (q4&7)*4
    // B-fill: 512 float4/iter -> 2 per thread: q2 = tid + 256*i; k = q2>>4, n4 = (q2&15)*4
    (void)a_m;

    for (int kt = 0; kt < KKT / BK; kt++) {          // 36 iterations
        const int kk0 = kt * BK;
        const int tap = kk0 / HH;                     // uniform per block (32 | 384)
        const int c0  = kk0 - tap * HH;

        // ---- load A tile: [BM][BK] with time shift + zero pad ----
#pragma unroll
        for (int i = 0; i < 4; i++) {
            const int q4 = tid + 256 * i;
            const int m  = q4 >> 3;
            const int k  = (q4 & 7) << 2;
            const int trow = t0 + m + tap - 1;
            float4 v = make_float4(0.f, 0.f, 0.f, 0.f);
            if (trow >= 0 && trow < TT)
                v = *reinterpret_cast<const float4*>(
                    A + (size_t)((b << 9) + trow) * HH + c0 + k);
            uint4 u;
            u.x = f2tf(v.x); u.y = f2tf(v.y); u.z = f2tf(v.z); u.w = f2tf(v.w);
            *reinterpret_cast<uint4*>(&As[m][k]) = u;
        }
        // ---- load B tile: [BK][BN] (f contiguous) ----
#pragma unroll
        for (int i = 0; i < 2; i++) {
            const int q2 = tid + 256 * i;
            const int k  = q2 >> 4;
            const int n  = (q2 & 15) << 2;
            const float4 v = *reinterpret_cast<const float4*>(
                Bw + (size_t)(tap * HH + c0 + k) * FF + f0 + n);
            uint4 u;
            u.x = f2tf(v.x); u.y = f2tf(v.y); u.z = f2tf(v.z); u.w = f2tf(v.w);
            *reinterpret_cast<uint4*>(&Bs[k][n]) = u;
        }
        __syncthreads();

        // ---- compute: 4 k-steps of 8 ----
#pragma unroll
        for (int s = 0; s < 4; s++) {
            const int ks = s * 8;
            unsigned a[2][4], bf[4][2];
#pragma unroll
            for (int mt = 0; mt < 2; mt++) {
                const int mr = m0w + mt * 16 + r;
                a[mt][0] = As[mr][ks + q];
                a[mt][1] = As[mr + 8][ks + q];
                a[mt][2] = As[mr][ks + q + 4];
                a[mt][3] = As[mr + 8][ks + q + 4];
            }
#pragma unroll
            for (int nt = 0; nt < 4; nt++) {
                const int nc = n0w + nt * 8 + r;
                bf[nt][0] = Bs[ks + q][nc];
                bf[nt][1] = Bs[ks + q + 4][nc];
            }
#pragma unroll
            for (int mt = 0; mt < 2; mt++)
#pragma unroll
                for (int nt = 0; nt < 4; nt++)
                    mma_tf32(acc[mt][nt], a[mt], bf[nt]);
        }
        __syncthreads();
    }

    // ---- epilogue: add bias, write C ----
#pragma unroll
    for (int mt = 0; mt < 2; mt++) {
        const int gm0 = m0 + m0w + mt * 16 + r;
#pragma unroll
        for (int nt = 0; nt < 4; nt++) {
            const int gf = f0 + n0w + nt * 8 + 2 * q;
            const float2 bv = *reinterpret_cast<const float2*>(bias + gf);
            float2 o0, o1;
            o0.x = acc[mt][nt][0] + bv.x;
            o0.y = acc[mt][nt][1] + bv.y;
            o1.x = acc[mt][nt][2] + bv.x;
            o1.y = acc[mt][nt][3] + bv.y;
            *reinterpret_cast<float2*>(C + (size_t)gm0 * FF + gf) = o0;
            *reinterpret_cast<float2*>(C + (size_t)(gm0 + 8) * FF + gf) = o1;
        }
    }
}

// ---------------------------------------------------------------------------
// Block reduction helper: 128 threads (4 warps)
// ---------------------------------------------------------------------------
__device__ __forceinline__ float block_sum128(float v, float* red, int tid) {
#pragma unroll
    for (int o = 16; o > 0; o >>= 1) v += __shfl_xor_sync(0xffffffffu, v, o);
    if ((tid & 31) == 0) red[tid >> 5] = v;
    __syncthreads();
    v = red[0] + red[1] + red[2] + red[3];
    __syncthreads();
    return v;
}

__device__ __forceinline__ float gelu_exact(float y) {
    return 0.5f * y * (1.0f + erff(y * 0.70710678118654752f));
}

// LayerNorm + exact GELU in place. One block per row, 128 threads (3 elems each).
__global__ void __launch_bounds__(128) ln_gelu_kernel(
    float* __restrict__ h, const float* __restrict__ g, const float* __restrict__ bb) {
    __shared__ float red[4];
    const int row = blockIdx.x, tid = threadIdx.x;
    float* p = h + (size_t)row * FF;
    float v0 = p[tid], v1 = p[tid + 128], v2 = p[tid + 256];
    const float mu = block_sum128(v0 + v1 + v2, red, tid) * (1.0f / FF);
    const float d0 = v0 - mu, d1 = v1 - mu, d2 = v2 - mu;
    const float var = block_sum128(d0 * d0 + d1 * d1 + d2 * d2, red, tid) * (1.0f / FF);
    const float rs = rsqrtf(var + 1e-5f);
    const float y0 = d0 * rs * g[tid] + bb[tid];
    const float y1 = d1 * rs * g[tid + 128] + bb[tid + 128];
    const float y2 = d2 * rs * g[tid + 256] + bb[tid + 256];
    p[tid]       = gelu_exact(y0);
    p[tid + 128] = gelu_exact(y1);
    p[tid + 256] = gelu_exact(y2);
}

// LayerNorm + GELU + linear(384->1) + ReLU -> length[row]
__global__ void __launch_bounds__(128) ln_gelu_lin_kernel(
    const float* __restrict__ h, const float* __restrict__ g, const float* __restrict__ bb,
    const float* __restrict__ lw, const float* __restrict__ lb, float* __restrict__ lenout) {
    __shared__ float red[4];
    const int row = blockIdx.x, tid = threadIdx.x;
    const float* p = h + (size_t)row * FF;
    float v0 = p[tid], v1 = p[tid + 128], v2 = p[tid + 256];
    const float mu = block_sum128(v0 + v1 + v2, red, tid) * (1.0f / FF);
    const float d0 = v0 - mu, d1 = v1 - mu, d2 = v2 - mu;
    const float var = block_sum128(d0 * d0 + d1 * d1 + d2 * d2, red, tid) * (1.0f / FF);
    const float rs = rsqrtf(var + 1e-5f);
    const float q0 = gelu_exact(d0 * rs * g[tid] + bb[tid]);
    const float q1 = gelu_exact(d1 * rs * g[tid + 128] + bb[tid + 128]);
    const float q2 = gelu_exact(d2 * rs * g[tid + 256] + bb[tid + 256]);
    const float dot = block_sum128(q0 * lw[tid] + q1 * lw[tid + 128] + q2 * lw[tid + 256],
                                   red, tid);
    if (tid == 0) lenout[row] = fmaxf(dot + lb[0], 0.0f);
}

// ---------------------------------------------------------------------------
// Duration scan + token map. One block per batch, 512 threads.
// ---------------------------------------------------------------------------
__global__ void __launch_bounds__(512) build_tok_kernel(
    const float* __restrict__ td, int* __restrict__ tok) {
    __shared__ int sc[TT];
    const int b = blockIdx.x, t = threadIdx.x;
    const int d = (int)rintf(expf(td[b * TT + t]));
    sc[t] = d;
    __syncthreads();
    for (int off = 1; off < TT; off <<= 1) {
        int v = sc[t];
        int add = (t >= off) ? sc[t - off] : 0;
        __syncthreads();
        sc[t] = v + add;
        __syncthreads();
    }
    const int end = sc[t];
    const int start = end - d;
    for (int l = start; l < end; l++) tok[b * LL + l] = t;
    __syncthreads();
    const int total = sc[TT - 1];
    for (int l = total + t; l < LL; l += TT) tok[b * LL + l] = -1;
}

// ---------------------------------------------------------------------------
// Expansion: out[b,l,:] = x[b,tok[b][l],:] (or zeros). float4 per thread.
// ---------------------------------------------------------------------------
__global__ void __launch_bounds__(256) expand_kernel(
    const float* __restrict__ x, const int* __restrict__ tok, float* __restrict__ out) {
    const unsigned idx = blockIdx.x * 256u + threadIdx.x;
    const int h4 = idx % H4;
    const int l  = (idx / H4) & (LL - 1);
    const int b  = idx / (H4 * LL);
    const int t  = tok[b * LL + l];
    float4 v = make_float4(0.f, 0.f, 0.f, 0.f);
    if (t >= 0)
        v = reinterpret_cast<const float4*>(x)[(size_t)(b * TT + t) * H4 + h4];
    reinterpret_cast<float4*>(out)[idx] = v;
}

// ---------------------------------------------------------------------------
extern "C" void kernel_launch(void* const* d_in, const int* in_sizes, int n_in,
                              void* d_out, int out_size) {
    const float* x   = (const float*)d_in[0];
    const float* td  = (const float*)d_in[1];
    const float* w1  = (const float*)d_in[2];
    const float* b1  = (const float*)d_in[3];
    const float* g1  = (const float*)d_in[4];
    const float* bb1 = (const float*)d_in[5];
    const float* w2  = (const float*)d_in[6];
    const float* b2  = (const float*)d_in[7];
    const float* g2  = (const float*)d_in[8];
    const float* bb2 = (const float*)d_in[9];
    const float* lw  = (const float*)d_in[10];
    const float* lb  = (const float*)d_in[11];

    float* out = (float*)d_out;
    float* lenout = out + OUT_OFF;

    float *wt1p, *wt2p, *h1p, *h2p;
    int* tokp;
    cudaGetSymbolAddress((void**)&wt1p, g_wt1);
    cudaGetSymbolAddress((void**)&wt2p, g_wt2);
    cudaGetSymbolAddress((void**)&h1p,  g_h1);
    cudaGetSymbolAddress((void**)&h2p,  g_h2);
    cudaGetSymbolAddress((void**)&tokp, g_tok);

    const int wele = FF * HH * KK3;
    wtrans_kernel<<<(wele + 255) / 256, 256>>>(w1, wt1p);
    wtrans_kernel<<<(wele + 255) / 256, 256>>>(w2, wt2p);

    dim3 ggrid(FF / BN, BT / BM);   // (6, 64)
    conv_gemm_tf32_kernel<<<ggrid, 256>>>(x, wt1p, b1, h1p);
    ln_gelu_kernel<<<BT, 128>>>(h1p, g1, bb1);
    conv_gemm_tf32_kernel<<<ggrid, 256>>>(h1p, wt2p, b2, h2p);
    ln_gelu_lin_kernel<<<BT, 128>>>(h2p, g2, bb2, lw, lb, lenout);

    build_tok_kernel<<<BB, TT>>>(td, tokp);
    expand_kernel<<<(BB * LL * H4) / 256, 256>>>(x, tokp, out);
}